// round 13
// baseline (speedup 1.0000x reference)
#include <cuda_runtime.h>
#include <cuda_bf16.h>
#include <cuda_fp16.h>
#include <cstdint>

#define DIM_FEAT 128
#define DIM_HID  256
#define DIM_LAT  64

#define N_MAX      200000
#define NUSER_MAX  100000
#define E_MAX      3400000
#define SCAN_BLK   1024

// Scratch (allocation-free rule: __device__ globals)
__device__ float   g_x[(size_t)N_MAX * DIM_LAT];
__device__ float   g_h[(size_t)N_MAX * DIM_LAT];
__device__ __half2 g_xh[(size_t)N_MAX * (DIM_LAT / 2)];
__device__ __half2 g_hh[(size_t)N_MAX * (DIM_LAT / 2)];
__device__ float   g_hid[(size_t)NUSER_MAX * DIM_HID];
__device__ int     g_degcnt[2 * N_MAX];                   // [0,N): deg(float), [N,2N): cnt(int)
__device__ int     g_ptr[N_MAX + 1];
__device__ int     g_cur[N_MAX];
__device__ int     g_bsum[256];
__device__ int2    g_pairs[E_MAX];

// ---------------------------------------------------------------------------
// Split-bf16 (3-term) GEMM body with ldmatrix fragment loads
// ---------------------------------------------------------------------------
__device__ __forceinline__ void mma_bf16(float& d0, float& d1, float& d2, float& d3,
                                         uint32_t a0, uint32_t a1, uint32_t a2, uint32_t a3,
                                         uint32_t b0, uint32_t b1)
{
    asm volatile("mma.sync.aligned.m16n8k16.row.col.f32.bf16.bf16.f32 "
                 "{%0,%1,%2,%3}, {%4,%5,%6,%7}, {%8,%9}, {%0,%1,%2,%3};"
                 : "+f"(d0), "+f"(d1), "+f"(d2), "+f"(d3)
                 : "r"(a0), "r"(a1), "r"(a2), "r"(a3), "r"(b0), "r"(b1));
}

__device__ __forceinline__ void ldsm_x4(uint32_t& r0, uint32_t& r1, uint32_t& r2,
                                        uint32_t& r3, uint32_t addr)
{
    asm volatile("ldmatrix.sync.aligned.m8n8.x4.shared.b16 {%0,%1,%2,%3}, [%4];"
                 : "=r"(r0), "=r"(r1), "=r"(r2), "=r"(r3) : "r"(addr));
}

__device__ __forceinline__ uint32_t smem_u32(const void* p) {
    uint32_t a;
    asm("{ .reg .u64 t; cvta.to.shared.u64 t, %1; cvt.u32.u64 %0, t; }"
        : "=r"(a) : "l"(p));
    return a;
}

__device__ __forceinline__ void split2_pack(float f0, float f1,
                                            uint32_t& hi, uint32_t& lo)
{
    uint32_t u0 = __float_as_uint(f0);
    uint32_t u1 = __float_as_uint(f1);
    hi = (u0 >> 16) | (u1 & 0xffff0000u);
    float r0 = f0 - __uint_as_float(u0 & 0xffff0000u);
    float r1 = f1 - __uint_as_float(u1 & 0xffff0000u);
    lo = (__float_as_uint(r0) >> 16) | (__float_as_uint(r1) & 0xffff0000u);
}

// KC=64 fixed. A planes: [BM][36] words (row-major, k packed by 2).
// B planes: [BN][36] words, n-major rows of k-pairs, XOR swizzle on 4-word groups.
template<int BM, int BN, int WGM, int WGN, bool LEAKY>
__device__ void gemm_body(const float* __restrict__ A, const float* __restrict__ B,
                          const float* __restrict__ bias, float* __restrict__ C,
                          int M, int K, int N, int bx, int by, uint32_t* smw)
{
    constexpr int NTHREADS = WGM * WGN * 32;
    constexpr int KC = 64;
    constexpr int KP = 32;
    constexpr int SR = 36;                 // row stride (words), 16B-aligned, bank-offset 4/row
    uint32_t* Ah = smw;                    // [BM][SR]
    uint32_t* Al = Ah + BM * SR;
    uint32_t* Bh = Al + BM * SR;           // [BN][SR]
    uint32_t* Bl = Bh + BN * SR;

    uint32_t sb = smem_u32(smw);
    const uint32_t A_PL = BM * SR * 4;     // plane size bytes (A)
    const uint32_t B_PL = BN * SR * 4;
    const uint32_t B0   = 2 * A_PL;        // Bh byte offset

    int tid  = threadIdx.x;
    int wid  = tid >> 5;
    int lane = tid & 31;
    int gid  = lane >> 2;
    int tig  = lane & 3;
    int wm   = wid % WGM;
    int wn   = wid / WGM;

    int row0 = by * BM;
    int bn0  = bx * BN;

    // ldmatrix lane-role setup
    int mG = lane >> 3;                    // matrix index 0..3
    int lr = lane & 7;
    uint32_t a_base = sb + (uint32_t)(((wm * 32 + ((mG & 1) << 3) + lr) * SR
                                       + ((mG >> 1) << 2)) * 4);
    int b_kw  = (mG & 1) << 2;             // k word-half within row
    int bn_q0 = wn * 32 + ((mG >> 1) << 3) + lr;
    int bn_q1 = bn_q0 + 16;
    uint32_t b_row0 = sb + B0 + (uint32_t)(bn_q0 * SR * 4);
    uint32_t b_row1 = sb + B0 + (uint32_t)(bn_q1 * SR * 4);
    int b_s0 = ((bn_q0 >> 3) & 3) << 3;
    int b_s1 = ((bn_q1 >> 3) & 3) << 3;

    float acc[2][4][4];
    #pragma unroll
    for (int i = 0; i < 2; i++)
        #pragma unroll
        for (int j = 0; j < 4; j++)
            #pragma unroll
            for (int q = 0; q < 4; q++) acc[i][j][q] = 0.f;

    for (int k0 = 0; k0 < K; k0 += KC) {
        // --- stage A [BM x KC] -> hi/lo planes ---
        #pragma unroll
        for (int i = tid; i < BM * (KC / 4); i += NTHREADS) {
            int r  = i >> 4;               // /(KC/4)=16
            int c4 = (i & 15) * 4;
            float4 v = make_float4(0.f, 0.f, 0.f, 0.f);
            int gr = row0 + r;
            if (gr < M) v = *reinterpret_cast<const float4*>(A + (size_t)gr * K + k0 + c4);
            uint32_t h0, l0, h1, l1;
            split2_pack(v.x, v.y, h0, l0);
            split2_pack(v.z, v.w, h1, l1);
            int base = r * SR + (c4 >> 1);
            Ah[base] = h0; Ah[base + 1] = h1;
            Al[base] = l0; Al[base + 1] = l1;
        }
        // --- stage B [KC x BN] -> n-major hi/lo planes with k-group swizzle ---
        #pragma unroll
        for (int i = tid; i < KP * BN; i += NTHREADS) {
            int n  = i % BN;
            int kp = i / BN;
            const float* bp = B + (size_t)(k0 + 2 * kp) * N + bn0 + n;
            float f0 = bp[0];
            float f1 = bp[N];
            uint32_t h, l;
            split2_pack(f0, f1, h, l);
            int sw = kp ^ (((n >> 3) & 3) << 3);
            Bh[n * SR + sw] = h;
            Bl[n * SR + sw] = l;
        }
        __syncthreads();

        #pragma unroll
        for (int ks = 0; ks < KC / 16; ks++) {
            uint32_t ah[2][4], al[2][4];
            ldsm_x4(ah[0][0], ah[0][1], ah[0][2], ah[0][3], a_base + ks * 32);
            ldsm_x4(ah[1][0], ah[1][1], ah[1][2], ah[1][3], a_base + 16 * SR * 4 + ks * 32);
            ldsm_x4(al[0][0], al[0][1], al[0][2], al[0][3], a_base + A_PL + ks * 32);
            ldsm_x4(al[1][0], al[1][1], al[1][2], al[1][3], a_base + A_PL + 16 * SR * 4 + ks * 32);

            uint32_t bw0 = (uint32_t)((((ks << 3) + b_kw) ^ b_s0) * 4);
            uint32_t bw1 = (uint32_t)((((ks << 3) + b_kw) ^ b_s1) * 4);
            uint32_t bh[4][2], bl[4][2];
            ldsm_x4(bh[0][0], bh[0][1], bh[1][0], bh[1][1], b_row0 + bw0);
            ldsm_x4(bh[2][0], bh[2][1], bh[3][0], bh[3][1], b_row1 + bw1);
            ldsm_x4(bl[0][0], bl[0][1], bl[1][0], bl[1][1], b_row0 + B_PL + bw0);
            ldsm_x4(bl[2][0], bl[2][1], bl[3][0], bl[3][1], b_row1 + B_PL + bw1);

            #pragma unroll
            for (int mt = 0; mt < 2; mt++)
                #pragma unroll
                for (int nt = 0; nt < 4; nt++) {
                    float* d = acc[mt][nt];
                    mma_bf16(d[0], d[1], d[2], d[3],
                             ah[mt][0], ah[mt][1], ah[mt][2], ah[mt][3],
                             bh[nt][0], bh[nt][1]);
                    mma_bf16(d[0], d[1], d[2], d[3],
                             al[mt][0], al[mt][1], al[mt][2], al[mt][3],
                             bh[nt][0], bh[nt][1]);
                    mma_bf16(d[0], d[1], d[2], d[3],
                             ah[mt][0], ah[mt][1], ah[mt][2], ah[mt][3],
                             bl[nt][0], bl[nt][1]);
                }
        }
        __syncthreads();
    }

    #pragma unroll
    for (int mt = 0; mt < 2; mt++) {
        int r1 = row0 + wm * 32 + mt * 16 + gid;
        int r2 = r1 + 8;
        #pragma unroll
        for (int nt = 0; nt < 4; nt++) {
            int col = bn0 + wn * 32 + nt * 8 + 2 * tig;
            float bv0 = bias[col], bv1 = bias[col + 1];
            float v0 = acc[mt][nt][0] + bv0;
            float v1 = acc[mt][nt][1] + bv1;
            float v2 = acc[mt][nt][2] + bv0;
            float v3 = acc[mt][nt][3] + bv1;
            if (LEAKY) {
                v0 = (v0 > 0.f) ? v0 : 0.01f * v0;
                v1 = (v1 > 0.f) ? v1 : 0.01f * v1;
                v2 = (v2 > 0.f) ? v2 : 0.01f * v2;
                v3 = (v3 > 0.f) ? v3 : 0.01f * v3;
            }
            if (r1 < M) *reinterpret_cast<float2*>(C + (size_t)r1 * N + col) = make_float2(v0, v1);
            if (r2 < M) *reinterpret_cast<float2*>(C + (size_t)r2 * N + col) = make_float2(v2, v3);
        }
    }
}

// ---------------------------------------------------------------------------
// fusedA: GEMM1 blocks ∥ degcnt blocks
// ---------------------------------------------------------------------------
__global__ void __launch_bounds__(256)
fusedA_kernel(const float* __restrict__ A, const float* __restrict__ W0,
              const float* __restrict__ b0, float* __restrict__ C, int M,
              const int* __restrict__ rows, const int* __restrict__ cols,
              float* __restrict__ deg, int* __restrict__ cnt, int E, int gemmBlocks)
{
    extern __shared__ uint32_t smw[];
    if ((int)blockIdx.x < gemmBlocks) {
        gemm_body<64, 128, 2, 4, true>(A, W0, b0, C, M, DIM_FEAT, DIM_HID,
                                       blockIdx.x & 1, blockIdx.x >> 1, smw);
    } else {
        int idx    = (blockIdx.x - gemmBlocks) * 256 + threadIdx.x;
        int stride = (gridDim.x - gemmBlocks) * 256;
        for (int i = idx; i < E; i += stride) {
            atomicAdd(&deg[rows[i]], 1.0f);
            atomicAdd(&cnt[cols[i]], 1);
        }
    }
}

// ---------------------------------------------------------------------------
// fusedB: GEMM2 blocks ∥ scatter blocks
// ---------------------------------------------------------------------------
__global__ void __launch_bounds__(128)
fusedB_kernel(const float* __restrict__ Hid, const float* __restrict__ W1,
              const float* __restrict__ b1, float* __restrict__ C, int M,
              const int* __restrict__ rows, const int* __restrict__ cols,
              const float* __restrict__ dis, int* __restrict__ cur,
              int2* __restrict__ pairs, int E, int gemmBlocks)
{
    extern __shared__ uint32_t smw[];
    if ((int)blockIdx.x < gemmBlocks) {
        gemm_body<64, 64, 2, 2, false>(Hid, W1, b1, C, M, DIM_HID, DIM_LAT,
                                       0, blockIdx.x, smw);
    } else {
        int idx    = (blockIdx.x - gemmBlocks) * 128 + threadIdx.x;
        int stride = (gridDim.x - gemmBlocks) * 128;
        for (int i = idx; i < E; i += stride) {
            int r = rows[i], c = cols[i];
            float s = dis[r] * dis[c];
            int pos = atomicAdd(&cur[c], 1);
            pairs[pos] = make_int2(r, __float_as_int(s));
        }
    }
}

// ---------------------------------------------------------------------------
// scan_block (+ fused dis)
// ---------------------------------------------------------------------------
__global__ void __launch_bounds__(SCAN_BLK)
scan_block_kernel(const int* __restrict__ cnt, float* __restrict__ deg,
                  int* __restrict__ out, int* __restrict__ bsum, int N)
{
    __shared__ int ws[32];
    int tid = threadIdx.x;
    int gid = blockIdx.x * SCAN_BLK + tid;
    if (gid < N) deg[gid] = rsqrtf(deg[gid]);
    int v = (gid < N) ? cnt[gid] : 0;
    int lane = tid & 31, wid = tid >> 5;
    int x = v;
    #pragma unroll
    for (int o = 1; o < 32; o <<= 1) {
        int y = __shfl_up_sync(0xffffffffu, x, o);
        if (lane >= o) x += y;
    }
    if (lane == 31) ws[wid] = x;
    __syncthreads();
    if (wid == 0) {
        int s = ws[lane];
        #pragma unroll
        for (int o = 1; o < 32; o <<= 1) {
            int y = __shfl_up_sync(0xffffffffu, s, o);
            if (lane >= o) s += y;
        }
        ws[lane] = s;
    }
    __syncthreads();
    int incl = x + ((wid > 0) ? ws[wid - 1] : 0);
    if (gid < N) out[gid] = incl - v;
    if (tid == SCAN_BLK - 1) bsum[blockIdx.x] = incl;
}

// ---------------------------------------------------------------------------
// scan_add (+ fused bsum prefix)
// ---------------------------------------------------------------------------
__global__ void __launch_bounds__(SCAN_BLK)
scan_add_kernel(int* __restrict__ ptr, const int* __restrict__ bsum,
                int* __restrict__ cur, int N, int E)
{
    __shared__ int red[32];
    int tid = threadIdx.x;
    int lane = tid & 31, wid = tid >> 5;

    int partial = 0;
    for (int t = tid; t < (int)blockIdx.x; t += SCAN_BLK) partial += bsum[t];
    #pragma unroll
    for (int o = 16; o > 0; o >>= 1) partial += __shfl_xor_sync(0xffffffffu, partial, o);
    if (lane == 0) red[wid] = partial;
    __syncthreads();
    if (wid == 0) {
        int v = (lane < SCAN_BLK / 32) ? red[lane] : 0;
        #pragma unroll
        for (int o = 16; o > 0; o >>= 1) v += __shfl_xor_sync(0xffffffffu, v, o);
        if (lane == 0) red[0] = v;
    }
    __syncthreads();
    int offset = red[0];

    int gid = blockIdx.x * SCAN_BLK + tid;
    if (gid < N) {
        int p = ptr[gid] + offset;
        ptr[gid] = p;
        cur[gid] = p;
    }
    if (gid == 0) ptr[N] = E;
}

// ---------------------------------------------------------------------------
// x = normalize(concat(preference, temp)), also emit fp16 mirror
// ---------------------------------------------------------------------------
__global__ void concat_norm_kernel(const float* __restrict__ pref,
                                   float* __restrict__ x,
                                   __half2* __restrict__ xh,
                                   int N, int num_user)
{
    int warp = (blockIdx.x * blockDim.x + threadIdx.x) >> 5;
    int lane = threadIdx.x & 31;
    int nwarps = (gridDim.x * blockDim.x) >> 5;
    for (int row = warp; row < N; row += nwarps) {
        const float* src = (row < num_user) ? (pref + (size_t)row * DIM_LAT)
                                            : (x + (size_t)row * DIM_LAT);
        float2 v = reinterpret_cast<const float2*>(src)[lane];
        float ss = v.x * v.x + v.y * v.y;
        #pragma unroll
        for (int o = 16; o > 0; o >>= 1) ss += __shfl_xor_sync(0xffffffffu, ss, o);
        float sc = 1.0f / fmaxf(sqrtf(ss), 1e-12f);
        float2 o2 = make_float2(v.x * sc, v.y * sc);
        reinterpret_cast<float2*>(x + (size_t)row * DIM_LAT)[lane] = o2;
        xh[(size_t)row * (DIM_LAT / 2) + lane] = __float22half2_rn(o2);
    }
}

// ---------------------------------------------------------------------------
// Pull conv with fp16 gathers
// ---------------------------------------------------------------------------
template<bool FUSE, bool WRITE_HALF>
__global__ void __launch_bounds__(256)
conv_pull_kernel(const int2* __restrict__ pairs, const int* __restrict__ ptr,
                 const __half2* __restrict__ srch,
                 const float* __restrict__ x0, const float* __restrict__ h0,
                 float* __restrict__ dst, __half2* __restrict__ dsth, int N)
{
    int warp = (blockIdx.x * blockDim.x + threadIdx.x) >> 5;
    if (warp >= N) return;
    int lane = threadIdx.x & 31;
    int beg = __ldg(ptr + warp);
    int end = __ldg(ptr + warp + 1);

    float2 acc = make_float2(0.f, 0.f);
    if (FUSE) {
        float2 a = reinterpret_cast<const float2*>(x0 + (size_t)warp * DIM_LAT)[lane];
        float2 b = reinterpret_cast<const float2*>(h0 + (size_t)warp * DIM_LAT)[lane];
        acc.x = a.x + b.x;
        acc.y = a.y + b.y;
    }

    int i = beg;
    for (; i + 2 <= end; i += 2) {
        int2 p0 = __ldg(pairs + i);
        int2 p1 = __ldg(pairs + i + 1);
        float2 v0 = __half22float2(__ldg(srch + (size_t)p0.x * (DIM_LAT / 2) + lane));
        float2 v1 = __half22float2(__ldg(srch + (size_t)p1.x * (DIM_LAT / 2) + lane));
        float s0 = __int_as_float(p0.y);
        float s1 = __int_as_float(p1.y);
        acc.x += s0 * v0.x + s1 * v1.x;
        acc.y += s0 * v0.y + s1 * v1.y;
    }
    if (i < end) {
        int2 p0 = __ldg(pairs + i);
        float2 v0 = __half22float2(__ldg(srch + (size_t)p0.x * (DIM_LAT / 2) + lane));
        float s0 = __int_as_float(p0.y);
        acc.x += s0 * v0.x;
        acc.y += s0 * v0.y;
    }
    reinterpret_cast<float2*>(dst + (size_t)warp * DIM_LAT)[lane] = acc;
    if (WRITE_HALF)
        dsth[(size_t)warp * (DIM_LAT / 2) + lane] = __float22half2_rn(acc);
}

extern "C" void kernel_launch(void* const* d_in, const int* in_sizes, int n_in,
                              void* d_out, int out_size)
{
    const int*   edge     = (const int*)d_in[0];
    const float* features = (const float*)d_in[1];
    const float* pref     = (const float*)d_in[2];
    const float* W0       = (const float*)d_in[3];
    const float* b0       = (const float*)d_in[4];
    const float* W1       = (const float*)d_in[5];
    const float* b1       = (const float*)d_in[6];

    int E        = in_sizes[0] / 2;
    int num_item = in_sizes[1] / DIM_FEAT;
    int num_user = in_sizes[2] / DIM_LAT;
    int N        = num_user + num_item;

    const int* rows = edge;
    const int* cols = edge + E;
    float* out = (float*)d_out;

    float *g_x_p, *g_h_p, *g_hid_p;
    __half2 *g_xh_p, *g_hh_p;
    int *g_degcnt_p, *g_ptr_p, *g_cur_p, *g_bsum_p;
    int2 *g_pairs_p;
    cudaGetSymbolAddress((void**)&g_x_p,      g_x);
    cudaGetSymbolAddress((void**)&g_h_p,      g_h);
    cudaGetSymbolAddress((void**)&g_xh_p,     g_xh);
    cudaGetSymbolAddress((void**)&g_hh_p,     g_hh);
    cudaGetSymbolAddress((void**)&g_hid_p,    g_hid);
    cudaGetSymbolAddress((void**)&g_degcnt_p, g_degcnt);
    cudaGetSymbolAddress((void**)&g_ptr_p,    g_ptr);
    cudaGetSymbolAddress((void**)&g_cur_p,    g_cur);
    cudaGetSymbolAddress((void**)&g_bsum_p,   g_bsum);
    cudaGetSymbolAddress((void**)&g_pairs_p,  g_pairs);

    float* g_deg_p = (float*)g_degcnt_p;      // [0, N)
    int*   g_cnt_p = g_degcnt_p + N;          // [N, 2N)

    // smem: (2*BM*36 + 2*BN*36) words * 4B
    const int smem1 = (2 * 64 * 36 + 2 * 128 * 36) * 4;   // 55296
    const int smem2 = (2 * 64 * 36 + 2 * 64 * 36) * 4;    // 36864
    cudaFuncSetAttribute(fusedA_kernel,
                         cudaFuncAttributeMaxDynamicSharedMemorySize, smem1);
    cudaFuncSetAttribute(fusedB_kernel,
                         cudaFuncAttributeMaxDynamicSharedMemorySize, smem2);

    int nb = (N + SCAN_BLK - 1) / SCAN_BLK;

    // one merged memset (deg + cnt)
    cudaMemsetAsync(g_degcnt_p, 0, (size_t)(2 * N) * sizeof(int));

    // 1) fusedA: GEMM1 || degcnt
    int gemm1Blocks = 2 * ((num_item + 63) / 64);
    const int AUX1 = 1536;
    fusedA_kernel<<<gemm1Blocks + AUX1, 256, smem1>>>(
        features, W0, b0, g_hid_p, num_item,
        rows, cols, g_deg_p, g_cnt_p, E, gemm1Blocks);

    // 2) scan_block (+dis)   3) scan_add (+bsum prefix)
    scan_block_kernel<<<nb, SCAN_BLK>>>(g_cnt_p, g_deg_p, g_ptr_p, g_bsum_p, N);
    scan_add_kernel<<<nb, SCAN_BLK>>>(g_ptr_p, g_bsum_p, g_cur_p, N, E);

    // 4) fusedB: GEMM2 || scatter   (ncu capture slot)
    int gemm2Blocks = (num_item + 63) / 64;
    const int AUX2 = 2048;
    fusedB_kernel<<<gemm2Blocks + AUX2, 128, smem2>>>(
        g_hid_p, W1, b1, g_x_p + (size_t)num_user * DIM_LAT, num_item,
        rows, cols, g_deg_p, g_cur_p, g_pairs_p, E, gemm2Blocks);

    // 5) concat + normalize (fp32 + fp16 mirror)
    concat_norm_kernel<<<1024, 256>>>(pref, g_x_p, g_xh_p, N, num_user);

    // 6) h = conv(x)   7) out = x + h + conv(h)
    int conv_blocks = (int)(((long long)N * 32 + 255) / 256);
    conv_pull_kernel<false, true><<<conv_blocks, 256>>>(
        g_pairs_p, g_ptr_p, g_xh_p, nullptr, nullptr, g_h_p, g_hh_p, N);
    conv_pull_kernel<true, false><<<conv_blocks, 256>>>(
        g_pairs_p, g_ptr_p, g_hh_p, g_x_p, g_h_p, out, nullptr, N);

    // output tuple tail: raw preference
    cudaMemcpyAsync(out + (size_t)N * DIM_LAT, pref,
                    (size_t)num_user * DIM_LAT * sizeof(float),
                    cudaMemcpyDeviceToDevice);
}

// round 14
// speedup vs baseline: 1.1735x; 1.1735x over previous
#include <cuda_runtime.h>
#include <cuda_bf16.h>
#include <cuda_fp16.h>
#include <cstdint>

#define DIM_FEAT 128
#define DIM_HID  256
#define DIM_LAT  64

#define N_MAX      200000
#define NUSER_MAX  100000
#define E_MAX      3400000
#define SCAN_BLK   1024

// Scratch (allocation-free rule: __device__ globals)
__device__ float   g_x[(size_t)N_MAX * DIM_LAT];
__device__ float   g_h[(size_t)N_MAX * DIM_LAT];
__device__ __half2 g_xh[(size_t)N_MAX * (DIM_LAT / 2)];
__device__ __half2 g_hh[(size_t)N_MAX * (DIM_LAT / 2)];
__device__ float   g_hid[(size_t)NUSER_MAX * DIM_HID];
__device__ int     g_degcnt[2 * N_MAX];                   // [0,N): deg(float), [N,2N): cnt(int)
__device__ int     g_ptr[N_MAX + 1];
__device__ int     g_cur[N_MAX];
__device__ int     g_bsum[256];
__device__ int2    g_pairs[E_MAX];

// ---------------------------------------------------------------------------
// Split-bf16 (3-term) GEMM via mma.sync.m16n8k16.bf16 (proven R8/R10 version)
// ---------------------------------------------------------------------------
__device__ __forceinline__ void mma_bf16(float& d0, float& d1, float& d2, float& d3,
                                         uint32_t a0, uint32_t a1, uint32_t a2, uint32_t a3,
                                         uint32_t b0, uint32_t b1)
{
    asm volatile("mma.sync.aligned.m16n8k16.row.col.f32.bf16.bf16.f32 "
                 "{%0,%1,%2,%3}, {%4,%5,%6,%7}, {%8,%9}, {%0,%1,%2,%3};"
                 : "+f"(d0), "+f"(d1), "+f"(d2), "+f"(d3)
                 : "r"(a0), "r"(a1), "r"(a2), "r"(a3), "r"(b0), "r"(b1));
}

__device__ __forceinline__ void split2_pack(float f0, float f1,
                                            uint32_t& hi, uint32_t& lo)
{
    uint32_t u0 = __float_as_uint(f0);
    uint32_t u1 = __float_as_uint(f1);
    hi = (u0 >> 16) | (u1 & 0xffff0000u);
    float r0 = f0 - __uint_as_float(u0 & 0xffff0000u);
    float r1 = f1 - __uint_as_float(u1 & 0xffff0000u);
    lo = (__float_as_uint(r0) >> 16) | (__float_as_uint(r1) & 0xffff0000u);
}

template<int BM, int BN, int KC, int WGM, int WGN, bool LEAKY>
__global__ void __launch_bounds__(WGM * WGN * 32)
gemm_bf16x3_kernel(const float* __restrict__ A, const float* __restrict__ B,
                   const float* __restrict__ bias, float* __restrict__ C,
                   int M, int K, int N)
{
    constexpr int NTHREADS = WGM * WGN * 32;
    constexpr int KP  = KC / 2;
    constexpr int SAW = KP + 1;
    constexpr int SBW = BN + 8;
    extern __shared__ uint32_t smw[];
    uint32_t* Ah = smw;
    uint32_t* Al = Ah + BM * SAW;
    uint32_t* Bh = Al + BM * SAW;
    uint32_t* Bl = Bh + KP * SBW;

    int tid  = threadIdx.x;
    int wid  = tid >> 5;
    int lane = tid & 31;
    int gid  = lane >> 2;
    int tig  = lane & 3;
    int wm   = wid % WGM;
    int wn   = wid / WGM;

    int row0 = blockIdx.y * BM;
    int bn0  = blockIdx.x * BN;

    float acc[2][4][4];
    #pragma unroll
    for (int i = 0; i < 2; i++)
        #pragma unroll
        for (int j = 0; j < 4; j++)
            #pragma unroll
            for (int q = 0; q < 4; q++) acc[i][j][q] = 0.f;

    for (int k0 = 0; k0 < K; k0 += KC) {
        #pragma unroll
        for (int i = tid; i < BM * (KC / 4); i += NTHREADS) {
            int r  = i / (KC / 4);
            int c4 = (i % (KC / 4)) * 4;
            float4 v = make_float4(0.f, 0.f, 0.f, 0.f);
            int gr = row0 + r;
            if (gr < M) v = *reinterpret_cast<const float4*>(A + (size_t)gr * K + k0 + c4);
            uint32_t h0, l0, h1, l1;
            split2_pack(v.x, v.y, h0, l0);
            split2_pack(v.z, v.w, h1, l1);
            int base = r * SAW + c4 / 2;
            Ah[base] = h0; Ah[base + 1] = h1;
            Al[base] = l0; Al[base + 1] = l1;
        }
        #pragma unroll
        for (int i = tid; i < KP * (BN / 4); i += NTHREADS) {
            int rp = i / (BN / 4);
            int c4 = (i % (BN / 4)) * 4;
            const float* bp = B + (size_t)(k0 + 2 * rp) * N + bn0 + c4;
            float4 u = *reinterpret_cast<const float4*>(bp);
            float4 w = *reinterpret_cast<const float4*>(bp + N);
            uint32_t h, l;
            int base = rp * SBW + c4;
            split2_pack(u.x, w.x, h, l); Bh[base]     = h; Bl[base]     = l;
            split2_pack(u.y, w.y, h, l); Bh[base + 1] = h; Bl[base + 1] = l;
            split2_pack(u.z, w.z, h, l); Bh[base + 2] = h; Bl[base + 2] = l;
            split2_pack(u.w, w.w, h, l); Bh[base + 3] = h; Bl[base + 3] = l;
        }
        __syncthreads();

        #pragma unroll
        for (int ks = 0; ks < KC / 16; ks++) {
            uint32_t ah[2][4], al[2][4];
            #pragma unroll
            for (int mt = 0; mt < 2; mt++) {
                int r1 = (wm * 32 + mt * 16 + gid) * SAW + ks * 8 + tig;
                int r2 = r1 + 8 * SAW;
                ah[mt][0] = Ah[r1];     al[mt][0] = Al[r1];
                ah[mt][1] = Ah[r2];     al[mt][1] = Al[r2];
                ah[mt][2] = Ah[r1 + 4]; al[mt][2] = Al[r1 + 4];
                ah[mt][3] = Ah[r2 + 4]; al[mt][3] = Al[r2 + 4];
            }
            uint32_t bh[4][2], bl[4][2];
            #pragma unroll
            for (int nt = 0; nt < 4; nt++) {
                int c1 = (ks * 8 + tig) * SBW + wn * 32 + nt * 8 + gid;
                int c2 = c1 + 4 * SBW;
                bh[nt][0] = Bh[c1]; bl[nt][0] = Bl[c1];
                bh[nt][1] = Bh[c2]; bl[nt][1] = Bl[c2];
            }
            #pragma unroll
            for (int mt = 0; mt < 2; mt++)
                #pragma unroll
                for (int nt = 0; nt < 4; nt++) {
                    float* d = acc[mt][nt];
                    mma_bf16(d[0], d[1], d[2], d[3],
                             ah[mt][0], ah[mt][1], ah[mt][2], ah[mt][3],
                             bh[nt][0], bh[nt][1]);
                    mma_bf16(d[0], d[1], d[2], d[3],
                             al[mt][0], al[mt][1], al[mt][2], al[mt][3],
                             bh[nt][0], bh[nt][1]);
                    mma_bf16(d[0], d[1], d[2], d[3],
                             ah[mt][0], ah[mt][1], ah[mt][2], ah[mt][3],
                             bl[nt][0], bl[nt][1]);
                }
        }
        __syncthreads();
    }

    #pragma unroll
    for (int mt = 0; mt < 2; mt++) {
        int r1 = row0 + wm * 32 + mt * 16 + gid;
        int r2 = r1 + 8;
        #pragma unroll
        for (int nt = 0; nt < 4; nt++) {
            int col = bn0 + wn * 32 + nt * 8 + 2 * tig;
            float bv0 = bias[col], bv1 = bias[col + 1];
            float v0 = acc[mt][nt][0] + bv0;
            float v1 = acc[mt][nt][1] + bv1;
            float v2 = acc[mt][nt][2] + bv0;
            float v3 = acc[mt][nt][3] + bv1;
            if (LEAKY) {
                v0 = (v0 > 0.f) ? v0 : 0.01f * v0;
                v1 = (v1 > 0.f) ? v1 : 0.01f * v1;
                v2 = (v2 > 0.f) ? v2 : 0.01f * v2;
                v3 = (v3 > 0.f) ? v3 : 0.01f * v3;
            }
            if (r1 < M) *reinterpret_cast<float2*>(C + (size_t)r1 * N + col) = make_float2(v0, v1);
            if (r2 < M) *reinterpret_cast<float2*>(C + (size_t)r2 * N + col) = make_float2(v2, v3);
        }
    }
}

// ---------------------------------------------------------------------------
// CSR build (kernels proven in R12/R13)
// ---------------------------------------------------------------------------
__global__ void degcnt_kernel(const int* __restrict__ rows, const int* __restrict__ cols,
                              float* __restrict__ deg, int* __restrict__ cnt, int E)
{
    int i = blockIdx.x * blockDim.x + threadIdx.x;
    if (i < E) {
        atomicAdd(&deg[rows[i]], 1.0f);
        atomicAdd(&cnt[cols[i]], 1);
    }
}

__global__ void __launch_bounds__(SCAN_BLK)
scan_block_kernel(const int* __restrict__ cnt, float* __restrict__ deg,
                  int* __restrict__ out, int* __restrict__ bsum, int N)
{
    __shared__ int ws[32];
    int tid = threadIdx.x;
    int gid = blockIdx.x * SCAN_BLK + tid;
    if (gid < N) deg[gid] = rsqrtf(deg[gid]);
    int v = (gid < N) ? cnt[gid] : 0;
    int lane = tid & 31, wid = tid >> 5;
    int x = v;
    #pragma unroll
    for (int o = 1; o < 32; o <<= 1) {
        int y = __shfl_up_sync(0xffffffffu, x, o);
        if (lane >= o) x += y;
    }
    if (lane == 31) ws[wid] = x;
    __syncthreads();
    if (wid == 0) {
        int s = ws[lane];
        #pragma unroll
        for (int o = 1; o < 32; o <<= 1) {
            int y = __shfl_up_sync(0xffffffffu, s, o);
            if (lane >= o) s += y;
        }
        ws[lane] = s;
    }
    __syncthreads();
    int incl = x + ((wid > 0) ? ws[wid - 1] : 0);
    if (gid < N) out[gid] = incl - v;
    if (tid == SCAN_BLK - 1) bsum[blockIdx.x] = incl;
}

__global__ void __launch_bounds__(SCAN_BLK)
scan_add_kernel(int* __restrict__ ptr, const int* __restrict__ bsum,
                int* __restrict__ cur, int N, int E)
{
    __shared__ int red[32];
    int tid = threadIdx.x;
    int lane = tid & 31, wid = tid >> 5;

    int partial = 0;
    for (int t = tid; t < (int)blockIdx.x; t += SCAN_BLK) partial += bsum[t];
    #pragma unroll
    for (int o = 16; o > 0; o >>= 1) partial += __shfl_xor_sync(0xffffffffu, partial, o);
    if (lane == 0) red[wid] = partial;
    __syncthreads();
    if (wid == 0) {
        int v = (lane < SCAN_BLK / 32) ? red[lane] : 0;
        #pragma unroll
        for (int o = 16; o > 0; o >>= 1) v += __shfl_xor_sync(0xffffffffu, v, o);
        if (lane == 0) red[0] = v;
    }
    __syncthreads();
    int offset = red[0];

    int gid = blockIdx.x * SCAN_BLK + tid;
    if (gid < N) {
        int p = ptr[gid] + offset;
        ptr[gid] = p;
        cur[gid] = p;
    }
    if (gid == 0) ptr[N] = E;
}

__global__ void scatter_kernel(const int* __restrict__ rows, const int* __restrict__ cols,
                               const float* __restrict__ dis,
                               int* __restrict__ cur, int2* __restrict__ pairs, int E)
{
    int i = blockIdx.x * blockDim.x + threadIdx.x;
    if (i < E) {
        int r = rows[i], c = cols[i];
        float s = dis[r] * dis[c];
        int pos = atomicAdd(&cur[c], 1);
        pairs[pos] = make_int2(r, __float_as_int(s));
    }
}

// ---------------------------------------------------------------------------
// x = normalize(concat(preference, temp)), also emit fp16 mirror
// ---------------------------------------------------------------------------
__global__ void concat_norm_kernel(const float* __restrict__ pref,
                                   float* __restrict__ x,
                                   __half2* __restrict__ xh,
                                   int N, int num_user)
{
    int warp = (blockIdx.x * blockDim.x + threadIdx.x) >> 5;
    int lane = threadIdx.x & 31;
    int nwarps = (gridDim.x * blockDim.x) >> 5;
    for (int row = warp; row < N; row += nwarps) {
        const float* src = (row < num_user) ? (pref + (size_t)row * DIM_LAT)
                                            : (x + (size_t)row * DIM_LAT);
        float2 v = reinterpret_cast<const float2*>(src)[lane];
        float ss = v.x * v.x + v.y * v.y;
        #pragma unroll
        for (int o = 16; o > 0; o >>= 1) ss += __shfl_xor_sync(0xffffffffu, ss, o);
        float sc = 1.0f / fmaxf(sqrtf(ss), 1e-12f);
        float2 o2 = make_float2(v.x * sc, v.y * sc);
        reinterpret_cast<float2*>(x + (size_t)row * DIM_LAT)[lane] = o2;
        xh[(size_t)row * (DIM_LAT / 2) + lane] = __float22half2_rn(o2);
    }
}

// ---------------------------------------------------------------------------
// Pull conv with fp16 gathers (proven R10 version)
// ---------------------------------------------------------------------------
template<bool FUSE, bool WRITE_HALF>
__global__ void __launch_bounds__(256)
conv_pull_kernel(const int2* __restrict__ pairs, const int* __restrict__ ptr,
                 const __half2* __restrict__ srch,
                 const float* __restrict__ x0, const float* __restrict__ h0,
                 float* __restrict__ dst, __half2* __restrict__ dsth, int N)
{
    int warp = (blockIdx.x * blockDim.x + threadIdx.x) >> 5;
    if (warp >= N) return;
    int lane = threadIdx.x & 31;
    int beg = __ldg(ptr + warp);
    int end = __ldg(ptr + warp + 1);

    float2 acc = make_float2(0.f, 0.f);
    if (FUSE) {
        float2 a = reinterpret_cast<const float2*>(x0 + (size_t)warp * DIM_LAT)[lane];
        float2 b = reinterpret_cast<const float2*>(h0 + (size_t)warp * DIM_LAT)[lane];
        acc.x = a.x + b.x;
        acc.y = a.y + b.y;
    }

    int i = beg;
    for (; i + 2 <= end; i += 2) {
        int2 p0 = __ldg(pairs + i);
        int2 p1 = __ldg(pairs + i + 1);
        float2 v0 = __half22float2(__ldg(srch + (size_t)p0.x * (DIM_LAT / 2) + lane));
        float2 v1 = __half22float2(__ldg(srch + (size_t)p1.x * (DIM_LAT / 2) + lane));
        float s0 = __int_as_float(p0.y);
        float s1 = __int_as_float(p1.y);
        acc.x += s0 * v0.x + s1 * v1.x;
        acc.y += s0 * v0.y + s1 * v1.y;
    }
    if (i < end) {
        int2 p0 = __ldg(pairs + i);
        float2 v0 = __half22float2(__ldg(srch + (size_t)p0.x * (DIM_LAT / 2) + lane));
        float s0 = __int_as_float(p0.y);
        acc.x += s0 * v0.x;
        acc.y += s0 * v0.y;
    }
    reinterpret_cast<float2*>(dst + (size_t)warp * DIM_LAT)[lane] = acc;
    if (WRITE_HALF)
        dsth[(size_t)warp * (DIM_LAT / 2) + lane] = __float22half2_rn(acc);
}

extern "C" void kernel_launch(void* const* d_in, const int* in_sizes, int n_in,
                              void* d_out, int out_size)
{
    const int*   edge     = (const int*)d_in[0];
    const float* features = (const float*)d_in[1];
    const float* pref     = (const float*)d_in[2];
    const float* W0       = (const float*)d_in[3];
    const float* b0       = (const float*)d_in[4];
    const float* W1       = (const float*)d_in[5];
    const float* b1       = (const float*)d_in[6];

    int E        = in_sizes[0] / 2;
    int num_item = in_sizes[1] / DIM_FEAT;
    int num_user = in_sizes[2] / DIM_LAT;
    int N        = num_user + num_item;

    const int* rows = edge;
    const int* cols = edge + E;
    float* out = (float*)d_out;

    float *g_x_p, *g_h_p, *g_hid_p;
    __half2 *g_xh_p, *g_hh_p;
    int *g_degcnt_p, *g_ptr_p, *g_cur_p, *g_bsum_p;
    int2 *g_pairs_p;
    cudaGetSymbolAddress((void**)&g_x_p,      g_x);
    cudaGetSymbolAddress((void**)&g_h_p,      g_h);
    cudaGetSymbolAddress((void**)&g_xh_p,     g_xh);
    cudaGetSymbolAddress((void**)&g_hh_p,     g_hh);
    cudaGetSymbolAddress((void**)&g_hid_p,    g_hid);
    cudaGetSymbolAddress((void**)&g_degcnt_p, g_degcnt);
    cudaGetSymbolAddress((void**)&g_ptr_p,    g_ptr);
    cudaGetSymbolAddress((void**)&g_cur_p,    g_cur);
    cudaGetSymbolAddress((void**)&g_bsum_p,   g_bsum);
    cudaGetSymbolAddress((void**)&g_pairs_p,  g_pairs);

    float* g_deg_p = (float*)g_degcnt_p;      // [0, N)
    int*   g_cnt_p = g_degcnt_p + N;          // [N, 2N)

    const int smem1 = (2 * 64 * 33 + 2 * 32 * 136) * 4;   // 51712 (KC=64, BN=128)
    const int smem2 = (2 * 64 * 33 + 2 * 32 * 72) * 4;    // 35328 (KC=64, BN=64)

    // One-time init on the correctness run (outside graph capture):
    // stream + events for fork-join capture, func attrs.
    static bool init_done = false;
    static cudaStream_t s2;
    static cudaEvent_t evFork, evJoin;
    if (!init_done) {
        cudaFuncSetAttribute(gemm_bf16x3_kernel<64, 128, 64, 2, 4, true>,
                             cudaFuncAttributeMaxDynamicSharedMemorySize, smem1);
        cudaStreamCreateWithFlags(&s2, cudaStreamNonBlocking);
        cudaEventCreateWithFlags(&evFork, cudaEventDisableTiming);
        cudaEventCreateWithFlags(&evJoin, cudaEventDisableTiming);
        init_done = true;
    }

    int nb = (N + SCAN_BLK - 1) / SCAN_BLK;

    // ---- fork: MLP chain on s2 ∥ CSR chain on default stream ----
    cudaEventRecord(evFork, 0);
    cudaStreamWaitEvent(s2, evFork, 0);

    // s2: GEMM1 -> GEMM2 -> concat+normalize -> output tail memcpy
    gemm_bf16x3_kernel<64, 128, 64, 2, 4, true>
        <<<dim3(2, (num_item + 63) / 64), 256, smem1, s2>>>(
            features, W0, b0, g_hid_p, num_item, DIM_FEAT, DIM_HID);
    gemm_bf16x3_kernel<64, 64, 64, 2, 2, false>
        <<<dim3(1, (num_item + 63) / 64), 128, smem2, s2>>>(
            g_hid_p, W1, b1, g_x_p + (size_t)num_user * DIM_LAT, num_item, DIM_HID, DIM_LAT);
    concat_norm_kernel<<<1024, 256, 0, s2>>>(pref, g_x_p, g_xh_p, N, num_user);
    cudaMemcpyAsync(out + (size_t)N * DIM_LAT, pref,
                    (size_t)num_user * DIM_LAT * sizeof(float),
                    cudaMemcpyDeviceToDevice, s2);

    // default stream: CSR build
    cudaMemsetAsync(g_degcnt_p, 0, (size_t)(2 * N) * sizeof(int));
    degcnt_kernel<<<(E + 255) / 256, 256>>>(rows, cols, g_deg_p, g_cnt_p, E);
    scan_block_kernel<<<nb, SCAN_BLK>>>(g_cnt_p, g_deg_p, g_ptr_p, g_bsum_p, N);
    scan_add_kernel<<<nb, SCAN_BLK>>>(g_ptr_p, g_bsum_p, g_cur_p, N, E);
    scatter_kernel<<<(E + 255) / 256, 256>>>(rows, cols, g_deg_p, g_cur_p, g_pairs_p, E);

    // ---- join: convs need both chains ----
    cudaEventRecord(evJoin, s2);
    cudaStreamWaitEvent(0, evJoin, 0);

    int conv_blocks = (int)(((long long)N * 32 + 255) / 256);
    conv_pull_kernel<false, true><<<conv_blocks, 256>>>(
        g_pairs_p, g_ptr_p, g_xh_p, nullptr, nullptr, g_h_p, g_hh_p, N);
    conv_pull_kernel<true, false><<<conv_blocks, 256>>>(
        g_pairs_p, g_ptr_p, g_hh_p, g_x_p, g_h_p, out, nullptr, N);
}